// round 2
// baseline (speedup 1.0000x reference)
#include <cuda_runtime.h>
#include <math.h>

#define BB   8192
#define TT   100
#define DD   44
#define NHH  64
#define LL   8
#define EPB  32          // batch elements per 128-thread block (4 lanes / element)

// Scratch (device globals: allocation-free rule)
__device__ float g_z0[BB * LL];
__device__ float g_kl[BB];
__device__ float g_perb[BB];

// ---------------------------------------------------------------------------
// Kernel 1: reverse-time tanh RNN encoder -> z0, kl per element
// ---------------------------------------------------------------------------
__global__ __launch_bounds__(128) void enc_kernel(
    const float* __restrict__ x, const float* __restrict__ mask,
    const float* __restrict__ eps,
    const float* __restrict__ Wi2h, const float* __restrict__ bi2h,
    const float* __restrict__ Wh2o, const float* __restrict__ bh2o)
{
    __shared__ float sW[(DD + NHH) * NHH];   // 6912
    __shared__ float sb[NHH];
    __shared__ float sWo[NHH * 2 * LL];      // 1024
    __shared__ float sbo[2 * LL];
    __shared__ float sxm[EPB][DD];           // masked x_t per element
    __shared__ float sh[EPB][68];            // h per element (padded: stride 68)

    const int tid = threadIdx.x;
    for (int i = tid; i < (DD + NHH) * NHH; i += 128) sW[i] = Wi2h[i];
    for (int i = tid; i < NHH; i += 128)              sb[i] = bi2h[i];
    for (int i = tid; i < NHH * 2 * LL; i += 128)     sWo[i] = Wh2o[i];
    if (tid < 2 * LL) sbo[tid] = bh2o[tid];
    // zero h
    for (int i = tid; i < EPB * 68; i += 128) (&sh[0][0])[i] = 0.0f;
    __syncthreads();

    const int e = tid >> 2;
    const int q = tid & 3;
    const int b = blockIdx.x * EPB + e;
    const float* xb = x    + (size_t)b * TT * DD;
    const float* mb = mask + (size_t)b * TT * DD;

    // prefetch t = T-1
    float rx[11], rm[11];
#pragma unroll
    for (int m = 0; m < 11; m++) {
        rx[m] = xb[(TT - 1) * DD + 4 * m + q];
        rm[m] = mb[(TT - 1) * DD + 4 * m + q];
    }

    for (int t = TT - 1; t >= 0; --t) {
        // publish masked x_t
#pragma unroll
        for (int m = 0; m < 11; m++) sxm[e][4 * m + q] = rx[m] * rm[m];
        __syncwarp();
        if (t > 0) {
#pragma unroll
            for (int m = 0; m < 11; m++) {
                rx[m] = xb[(t - 1) * DD + 4 * m + q];
                rm[m] = mb[(t - 1) * DD + 4 * m + q];
            }
        }
        // acc_j = b_j + sum_k in_k * W[k][j], thread owns j = 8m+2q+{0,1}
        float2 acc[8];
#pragma unroll
        for (int m = 0; m < 8; m++) acc[m] = *(const float2*)&sb[8 * m + 2 * q];
#pragma unroll 4
        for (int k = 0; k < DD; k++) {
            const float v = sxm[e][k];
            const float2* wr = (const float2*)&sW[k * NHH];
#pragma unroll
            for (int m = 0; m < 8; m++) {
                float2 w = wr[4 * m + q];
                acc[m].x += v * w.x; acc[m].y += v * w.y;
            }
        }
#pragma unroll 4
        for (int k = 0; k < NHH; k++) {
            const float v = sh[e][k];
            const float2* wr = (const float2*)&sW[(DD + k) * NHH];
#pragma unroll
            for (int m = 0; m < 8; m++) {
                float2 w = wr[4 * m + q];
                acc[m].x += v * w.x; acc[m].y += v * w.y;
            }
        }
        __syncwarp();
#pragma unroll
        for (int m = 0; m < 8; m++) {
            sh[e][8 * m + 2 * q]     = tanhf(acc[m].x);
            sh[e][8 * m + 2 * q + 1] = tanhf(acc[m].y);
        }
        __syncwarp();
    }

    // out = h_final @ Wh2o + bh2o  (all 4 lanes compute redundantly; broadcast reads)
    float out[16];
#pragma unroll
    for (int o = 0; o < 16; o++) out[o] = sbo[o];
    for (int k = 0; k < NHH; k++) {
        const float v = sh[e][k];
#pragma unroll
        for (int o = 0; o < 16; o++) out[o] += v * sWo[k * 16 + o];
    }
    if (q == 0) {
        float kl = 0.0f;
#pragma unroll
        for (int l = 0; l < LL; l++) {
            const float mean = out[l];
            const float lv   = out[LL + l];
            g_z0[b * LL + l] = eps[b * LL + l] * __expf(0.5f * lv) + mean;
            kl += -0.5f * lv + (__expf(lv) + mean * mean) * 0.5f - 0.5f;
        }
        g_kl[b] = kl;
    }
}

// ---------------------------------------------------------------------------
// Kernel 2: RK4 latent ODE + decoder + Gaussian NLL, fused per element
// ---------------------------------------------------------------------------
__global__ __launch_bounds__(128) void ode_kernel(
    const float* __restrict__ x, const float* __restrict__ mask,
    const float* __restrict__ Wf1, const float* __restrict__ bf1,
    const float* __restrict__ Wf2, const float* __restrict__ bf2,
    const float* __restrict__ Wf3, const float* __restrict__ bf3,
    const float* __restrict__ Wd1, const float* __restrict__ bd1,
    const float* __restrict__ Wd2, const float* __restrict__ bd2)
{
    __shared__ float sWf1[LL * NHH], sbf1[NHH];
    __shared__ float sWf2[NHH * NHH], sbf2[NHH];
    __shared__ float sWf3[NHH * LL], sbf3[LL];
    __shared__ float sWd1[LL * NHH], sbd1[NHH];
    __shared__ float sWd2[NHH * DD], sbd2[DD];
    __shared__ float sh1[EPB][68];   // shared scratch for h1 / hd (per-element row)

    const int tid = threadIdx.x;
    for (int i = tid; i < LL * NHH; i += 128) { sWf1[i] = Wf1[i]; sWd1[i] = Wd1[i]; }
    for (int i = tid; i < NHH; i += 128) { sbf1[i] = bf1[i]; sbf2[i] = bf2[i]; sbd1[i] = bd1[i]; }
    for (int i = tid; i < NHH * NHH; i += 128) sWf2[i] = Wf2[i];
    for (int i = tid; i < NHH * LL; i += 128)  sWf3[i] = Wf3[i];
    for (int i = tid; i < NHH * DD; i += 128)  sWd2[i] = Wd2[i];
    if (tid < LL) sbf3[tid] = bf3[tid];
    if (tid < DD) sbd2[tid] = bd2[tid];
    __syncthreads();

    const int e = tid >> 2;
    const int q = tid & 3;
    const int b = blockIdx.x * EPB + e;
    const float* xb = x    + (size_t)b * TT * DD;
    const float* mb = mask + (size_t)b * TT * DD;

    float z[8];
#pragma unroll
    for (int l = 0; l < 8; l++) z[l] = g_z0[b * LL + l];

    const float dt = 1.0f / (float)(TT - 1);
    float sse = 0.0f;

    for (int t = 0; t < TT; t++) {
        float rx[11], rm[11];
#pragma unroll
        for (int m = 0; m < 11; m++) {
            rx[m] = xb[t * DD + 4 * m + q];
            rm[m] = mb[t * DD + 4 * m + q];
        }

        // ---- decoder: hd = relu(z @ Wd1 + bd1) ----
        float2 hd[8];
#pragma unroll
        for (int m = 0; m < 8; m++) hd[m] = *(const float2*)&sbd1[8 * m + 2 * q];
#pragma unroll
        for (int k = 0; k < LL; k++) {
            const float v = z[k];
            const float2* wr = (const float2*)&sWd1[k * NHH];
#pragma unroll
            for (int m = 0; m < 8; m++) {
                float2 w = wr[4 * m + q];
                hd[m].x += v * w.x; hd[m].y += v * w.y;
            }
        }
        __syncwarp();
#pragma unroll
        for (int m = 0; m < 8; m++) {
            sh1[e][8 * m + 2 * q]     = fmaxf(hd[m].x, 0.0f);
            sh1[e][8 * m + 2 * q + 1] = fmaxf(hd[m].y, 0.0f);
        }
        __syncwarp();
        // px = hd @ Wd2 + bd2 ; thread owns d = 4m+q
        float px[11];
#pragma unroll
        for (int m = 0; m < 11; m++) px[m] = sbd2[4 * m + q];
#pragma unroll 4
        for (int k = 0; k < NHH; k++) {
            const float v = sh1[e][k];
#pragma unroll
            for (int m = 0; m < 11; m++) px[m] += v * sWd2[k * DD + 4 * m + q];
        }
        // ---- loss contribution ----
#pragma unroll
        for (int m = 0; m < 11; m++) {
            const float xv = rx[m];
            const float mx = xv * rm[m];
            float d = xv - px[m];
            d = (mx != 0.0f) ? 0.0f : d;
            sse += d * d;
        }

        // ---- RK4 step ----
        if (t < TT - 1) {
            float zacc[8], ztmp[8];
#pragma unroll
            for (int l = 0; l < 8; l++) { zacc[l] = z[l]; ztmp[l] = z[l]; }
#pragma unroll 1
            for (int s = 0; s < 4; s++) {
                const float wco = (s == 0 || s == 3) ? dt / 6.0f : dt / 3.0f;
                const float cco = (s == 2) ? dt : 0.5f * dt;
                // h1 = elu(ztmp @ Wf1 + bf1)
                float2 h1[8];
#pragma unroll
                for (int m = 0; m < 8; m++) h1[m] = *(const float2*)&sbf1[8 * m + 2 * q];
#pragma unroll
                for (int k = 0; k < LL; k++) {
                    const float v = ztmp[k];
                    const float2* wr = (const float2*)&sWf1[k * NHH];
#pragma unroll
                    for (int m = 0; m < 8; m++) {
                        float2 w = wr[4 * m + q];
                        h1[m].x += v * w.x; h1[m].y += v * w.y;
                    }
                }
                __syncwarp();
#pragma unroll
                for (int m = 0; m < 8; m++) {
                    const float a = h1[m].x, c = h1[m].y;
                    sh1[e][8 * m + 2 * q]     = (a > 0.0f) ? a : (__expf(a) - 1.0f);
                    sh1[e][8 * m + 2 * q + 1] = (c > 0.0f) ? c : (__expf(c) - 1.0f);
                }
                __syncwarp();
                // h2 = elu(h1 @ Wf2 + bf2)
                float2 h2[8];
#pragma unroll
                for (int m = 0; m < 8; m++) h2[m] = *(const float2*)&sbf2[8 * m + 2 * q];
#pragma unroll 4
                for (int k = 0; k < NHH; k++) {
                    const float v = sh1[e][k];
                    const float2* wr = (const float2*)&sWf2[k * NHH];
#pragma unroll
                    for (int m = 0; m < 8; m++) {
                        float2 w = wr[4 * m + q];
                        h2[m].x += v * w.x; h2[m].y += v * w.y;
                    }
                }
#pragma unroll
                for (int m = 0; m < 8; m++) {
                    const float a = h2[m].x, c = h2[m].y;
                    h2[m].x = (a > 0.0f) ? a : (__expf(a) - 1.0f);
                    h2[m].y = (c > 0.0f) ? c : (__expf(c) - 1.0f);
                }
                // fout = h2 @ Wf3 + bf3 : per-lane partials, quad butterfly
                float pf[8];
#pragma unroll
                for (int l = 0; l < 8; l++) pf[l] = 0.0f;
#pragma unroll
                for (int m = 0; m < 8; m++) {
                    const int k0 = 8 * m + 2 * q;
                    const float4* w0 = (const float4*)&sWf3[k0 * LL];
                    float4 wa = w0[0], wb = w0[1];
                    pf[0] += h2[m].x * wa.x; pf[1] += h2[m].x * wa.y;
                    pf[2] += h2[m].x * wa.z; pf[3] += h2[m].x * wa.w;
                    pf[4] += h2[m].x * wb.x; pf[5] += h2[m].x * wb.y;
                    pf[6] += h2[m].x * wb.z; pf[7] += h2[m].x * wb.w;
                    const float4* w1 = (const float4*)&sWf3[(k0 + 1) * LL];
                    float4 wc = w1[0], wd = w1[1];
                    pf[0] += h2[m].y * wc.x; pf[1] += h2[m].y * wc.y;
                    pf[2] += h2[m].y * wc.z; pf[3] += h2[m].y * wc.w;
                    pf[4] += h2[m].y * wd.x; pf[5] += h2[m].y * wd.y;
                    pf[6] += h2[m].y * wd.z; pf[7] += h2[m].y * wd.w;
                }
#pragma unroll
                for (int l = 0; l < 8; l++) {
                    pf[l] += __shfl_xor_sync(0xffffffffu, pf[l], 1);
                    pf[l] += __shfl_xor_sync(0xffffffffu, pf[l], 2);
                }
#pragma unroll
                for (int l = 0; l < 8; l++) {
                    const float fo = pf[l] + sbf3[l];
                    zacc[l] += wco * fo;
                    ztmp[l] = z[l] + cco * fo;
                }
            }
#pragma unroll
            for (int l = 0; l < 8; l++) z[l] = zacc[l];
        }
    }

    // quad-reduce SSE, write per-element loss term
    sse += __shfl_xor_sync(0xffffffffu, sse, 1);
    sse += __shfl_xor_sync(0xffffffffu, sse, 2);
    if (q == 0) {
        const float nlv = 2.0f * logf(0.3f);
        const float l2p = logf(6.283185307179586f);
        const float logpx = -0.5f * ((float)(TT * DD) * (l2p + nlv) + sse / expf(nlv));
        g_perb[b] = -logpx + g_kl[b];
    }
}

// ---------------------------------------------------------------------------
// Kernel 3: mean reduction -> d_out[0]
// ---------------------------------------------------------------------------
__global__ void reduce_kernel(float* __restrict__ out)
{
    __shared__ float s[1024];
    const int tid = threadIdx.x;
    float v = 0.0f;
    for (int i = tid; i < BB; i += 1024) v += g_perb[i];
    s[tid] = v;
    __syncthreads();
    for (int st = 512; st > 0; st >>= 1) {
        if (tid < st) s[tid] += s[tid + st];
        __syncthreads();
    }
    if (tid == 0) out[0] = s[0] / (float)BB;
}

// ---------------------------------------------------------------------------
extern "C" void kernel_launch(void* const* d_in, const int* in_sizes, int n_in,
                              void* d_out, int out_size)
{
    const float* x    = (const float*)d_in[0];
    const float* mask = (const float*)d_in[1];
    const float* eps  = (const float*)d_in[2];
    const float* Wi2h = (const float*)d_in[3];
    const float* bi2h = (const float*)d_in[4];
    const float* Wh2o = (const float*)d_in[5];
    const float* bh2o = (const float*)d_in[6];
    const float* Wf1  = (const float*)d_in[7];
    const float* bf1  = (const float*)d_in[8];
    const float* Wf2  = (const float*)d_in[9];
    const float* bf2  = (const float*)d_in[10];
    const float* Wf3  = (const float*)d_in[11];
    const float* bf3  = (const float*)d_in[12];
    const float* Wd1  = (const float*)d_in[13];
    const float* bd1  = (const float*)d_in[14];
    const float* Wd2  = (const float*)d_in[15];
    const float* bd2  = (const float*)d_in[16];

    enc_kernel<<<BB / EPB, 128>>>(x, mask, eps, Wi2h, bi2h, Wh2o, bh2o);
    ode_kernel<<<BB / EPB, 128>>>(x, mask, Wf1, bf1, Wf2, bf2, Wf3, bf3,
                                  Wd1, bd1, Wd2, bd2);
    reduce_kernel<<<1, 1024>>>((float*)d_out);
}

// round 3
// speedup vs baseline: 1.0351x; 1.0351x over previous
#include <cuda_runtime.h>
#include <math.h>

#define BB 8192
#define TT 100
#define DD 44
#define NHH 64
#define LL 8

typedef unsigned long long u64;

// ---------------- packed f32x2 helpers (sm_103a) ----------------
__device__ __forceinline__ void ffma2(u64& d, u64 a, u64 b) {
    asm("fma.rn.f32x2 %0, %1, %2, %0;" : "+l"(d) : "l"(a), "l"(b));
}
__device__ __forceinline__ u64 pack2(float lo, float hi) {
    u64 r;
    asm("mov.b64 %0, {%1, %2};" : "=l"(r)
        : "r"(__float_as_uint(lo)), "r"(__float_as_uint(hi)));
    return r;
}
__device__ __forceinline__ u64 splat2(float v) {
    u64 r;
    asm("mov.b64 %0, {%1, %1};" : "=l"(r) : "r"(__float_as_uint(v)));
    return r;
}
__device__ __forceinline__ float2 unpack2(u64 v) {
    unsigned lo, hi;
    asm("mov.b64 {%0, %1}, %2;" : "=r"(lo), "=r"(hi) : "l"(v));
    return make_float2(__uint_as_float(lo), __uint_as_float(hi));
}
__device__ __forceinline__ u64 d2u(double d) { return (u64)__double_as_longlong(d); }

// ---------------- device scratch ----------------
__device__ float g_z0[BB * LL];
__device__ float g_kl[BB];
__device__ float g_perb[BB];

// ---------------------------------------------------------------------------
// Kernel 1: reverse-time tanh RNN encoder.
// 128 thr = 4 warps; warp handles 8 elements. lane = sub*8+jl;
// sub in [0,4): element pair e = warp*8 + 2*sub + g, g in {0,1}.
// lane jl owns hidden cols 8jl..8jl+7 (4 packed pairs) for both elements.
// ---------------------------------------------------------------------------
__global__ __launch_bounds__(128) void enc_kernel(
    const float* __restrict__ x, const float* __restrict__ mask,
    const float* __restrict__ eps,
    const float* __restrict__ Wi2h, const float* __restrict__ bi2h,
    const float* __restrict__ Wh2o, const float* __restrict__ bh2o)
{
    __shared__ __align__(16) float sW[108 * 64];
    __shared__ __align__(16) float sWo[64 * 16];
    __shared__ __align__(16) float sb[64];
    __shared__ __align__(16) float sbo[16];
    __shared__ __align__(16) float sxh[32 * 116];   // per elem: x[0..44) h[44..108)

    const int tid = threadIdx.x;
    for (int i = tid; i < 108 * 64; i += 128) sW[i] = Wi2h[i];
    for (int i = tid; i < 64 * 16; i += 128)  sWo[i] = Wh2o[i];
    if (tid < 64) sb[tid] = bi2h[tid];
    if (tid < 16) sbo[tid] = bh2o[tid];
    for (int i = tid; i < 32 * 116; i += 128) sxh[i] = 0.0f;
    __syncthreads();

    const int lane = tid & 31, warp = tid >> 5;
    const int jl = lane & 7, sub = lane >> 3;
    const int eW = warp * 8;
    const int b0 = blockIdx.x * 32;

    float* row[2];
    row[0] = &sxh[(eW + 2 * sub) * 116];
    row[1] = &sxh[(eW + 2 * sub + 1) * 116];

    u64 bir[4];
#pragma unroll
    for (int p = 0; p < 4; p++) bir[p] = d2u(((const double*)sb)[4 * jl + p]);

    // prefetch t = T-1 : 8 elements * 44 = 352 = 11 * 32
    float rx[11], rmk[11];
#pragma unroll
    for (int r = 0; r < 11; r++) {
        const int idx = r * 32 + lane;
        const int el = idx / 44, d = idx % 44;
        const size_t off = (size_t)(b0 + eW + el) * TT * DD + (size_t)(TT - 1) * DD + d;
        rx[r] = x[off]; rmk[r] = mask[off];
    }

    for (int t = TT - 1; t >= 0; --t) {
#pragma unroll
        for (int r = 0; r < 11; r++) {
            const int idx = r * 32 + lane;
            sxh[(eW + idx / 44) * 116 + idx % 44] = rx[r] * rmk[r];
        }
        __syncwarp();
        if (t > 0) {
#pragma unroll
            for (int r = 0; r < 11; r++) {
                const int idx = r * 32 + lane;
                const int el = idx / 44, d = idx % 44;
                const size_t off = (size_t)(b0 + eW + el) * TT * DD + (size_t)(t - 1) * DD + d;
                rx[r] = x[off]; rmk[r] = mask[off];
            }
        }

        u64 acc[2][4];
#pragma unroll
        for (int p = 0; p < 4; p++) { acc[0][p] = bir[p]; acc[1][p] = bir[p]; }
#pragma unroll 4
        for (int k = 0; k < 108; k++) {
            const double2* wr = (const double2*)&sW[k * 64 + 8 * jl];
            const double2 wa = wr[0], wb = wr[1];
            const u64 w0 = d2u(wa.x), w1 = d2u(wa.y), w2 = d2u(wb.x), w3 = d2u(wb.y);
            const u64 v0 = splat2(row[0][k]);
            const u64 v1 = splat2(row[1][k]);
            ffma2(acc[0][0], w0, v0); ffma2(acc[0][1], w1, v0);
            ffma2(acc[0][2], w2, v0); ffma2(acc[0][3], w3, v0);
            ffma2(acc[1][0], w0, v1); ffma2(acc[1][1], w1, v1);
            ffma2(acc[1][2], w2, v1); ffma2(acc[1][3], w3, v1);
        }
        __syncwarp();
#pragma unroll
        for (int g = 0; g < 2; g++)
#pragma unroll
            for (int p = 0; p < 4; p++) {
                const float2 a = unpack2(acc[g][p]);
                *(float2*)&row[g][44 + 8 * jl + 2 * p] =
                    make_float2(tanhf(a.x), tanhf(a.y));
            }
        __syncwarp();
    }

    // out = h_final @ Wh2o + bh2o ; lane owns output pair (2jl, 2jl+1)
    u64 oacc[2];
    oacc[0] = oacc[1] = d2u(((const double*)sbo)[jl]);
#pragma unroll 4
    for (int k = 0; k < 64; k++) {
        const u64 w = d2u(((const double*)sWo)[k * 8 + jl]);
        ffma2(oacc[0], w, splat2(row[0][44 + k]));
        ffma2(oacc[1], w, splat2(row[1][44 + k]));
    }
#pragma unroll
    for (int g = 0; g < 2; g++) {
        const u64 oth = __shfl_xor_sync(0xffffffffu, oacc[g], 4);
        const int b = b0 + eW + 2 * sub + g;
        float kl = 0.0f;
        if (jl < 4) {
            const float2 mn = unpack2(oacc[g]);
            const float2 lv = unpack2(oth);
            const float2 ep = *(const float2*)&eps[b * LL + 2 * jl];
            float2 z0;
            z0.x = ep.x * __expf(0.5f * lv.x) + mn.x;
            z0.y = ep.y * __expf(0.5f * lv.y) + mn.y;
            *(float2*)&g_z0[b * LL + 2 * jl] = z0;
            kl = -0.5f * lv.x + (__expf(lv.x) + mn.x * mn.x) * 0.5f - 0.5f
               + -0.5f * lv.y + (__expf(lv.y) + mn.y * mn.y) * 0.5f - 0.5f;
        }
        kl += __shfl_xor_sync(0xffffffffu, kl, 1);
        kl += __shfl_xor_sync(0xffffffffu, kl, 2);
        if (jl == 0) g_kl[b] = kl;
    }
}

// ---------------------------------------------------------------------------
// Kernel 2: RK4 latent ODE + decoder + Gaussian NLL (fused).
// Same lane layout. Per-element smem row (stride 140):
//   [0..8) z / ztmp   [8..72) h1/hd   [72..136) h2
// ---------------------------------------------------------------------------
__global__ __launch_bounds__(128) void ode_kernel(
    const float* __restrict__ x, const float* __restrict__ mask,
    const float* __restrict__ Wf1, const float* __restrict__ bf1,
    const float* __restrict__ Wf2, const float* __restrict__ bf2,
    const float* __restrict__ Wf3, const float* __restrict__ bf3,
    const float* __restrict__ Wd1, const float* __restrict__ bd1,
    const float* __restrict__ Wd2, const float* __restrict__ bd2)
{
    __shared__ __align__(16) float sWf1[8 * 64], sWf2[64 * 64], sWf3[64 * 8];
    __shared__ __align__(16) float sWd1[8 * 64], sWd2[64 * 48];
    __shared__ __align__(16) float sbf1[64], sbf2[64], sbf3[8];
    __shared__ __align__(16) float sbd1[64], sbd2[48];
    __shared__ __align__(16) float sv[32 * 140];

    const int tid = threadIdx.x;
    for (int i = tid; i < 8 * 64; i += 128) { sWf1[i] = Wf1[i]; sWd1[i] = Wd1[i]; }
    for (int i = tid; i < 64 * 64; i += 128) sWf2[i] = Wf2[i];
    for (int i = tid; i < 64 * 8; i += 128)  sWf3[i] = Wf3[i];
    for (int i = tid; i < 64 * 48; i += 128) sWd2[i] = 0.0f;
    if (tid < 64) { sbf1[tid] = bf1[tid]; sbf2[tid] = bf2[tid]; sbd1[tid] = bd1[tid]; }
    if (tid < 8)  sbf3[tid] = bf3[tid];
    if (tid < 48) sbd2[tid] = (tid < 44) ? bd2[tid] : 0.0f;
    __syncthreads();
    for (int i = tid; i < 64 * 44; i += 128) sWd2[(i / 44) * 48 + (i % 44)] = Wd2[i];
    __syncthreads();

    const int lane = tid & 31, warp = tid >> 5;
    const int jl = lane & 7, sub = lane >> 3;
    const int eW = warp * 8;
    const int b0 = blockIdx.x * 32;

    float* row[2]; int bg[2];
    row[0] = &sv[(eW + 2 * sub) * 140];
    row[1] = &sv[(eW + 2 * sub + 1) * 140];
    bg[0] = b0 + eW + 2 * sub;
    bg[1] = bg[0] + 1;

    float zr[2];
#pragma unroll
    for (int g = 0; g < 2; g++) {
        zr[g] = g_z0[bg[g] * LL + jl];
        row[g][jl] = zr[g];
    }
    __syncwarp();

    const float dt = 1.0f / (float)(TT - 1);
    float sse[2] = {0.0f, 0.0f};

    for (int t = 0; t < TT; t++) {
        // ---- decoder layer 1: hd = relu(z @ Wd1 + bd1) ----
        {
            u64 hd[2][4];
#pragma unroll
            for (int p = 0; p < 4; p++) {
                const u64 bv = d2u(((const double*)sbd1)[4 * jl + p]);
                hd[0][p] = bv; hd[1][p] = bv;
            }
#pragma unroll
            for (int k = 0; k < 8; k++) {
                const double2* wr = (const double2*)&sWd1[k * 64 + 8 * jl];
                const double2 wa = wr[0], wb = wr[1];
                const u64 w0 = d2u(wa.x), w1 = d2u(wa.y), w2 = d2u(wb.x), w3 = d2u(wb.y);
                const u64 v0 = splat2(row[0][k]), v1 = splat2(row[1][k]);
                ffma2(hd[0][0], w0, v0); ffma2(hd[0][1], w1, v0);
                ffma2(hd[0][2], w2, v0); ffma2(hd[0][3], w3, v0);
                ffma2(hd[1][0], w0, v1); ffma2(hd[1][1], w1, v1);
                ffma2(hd[1][2], w2, v1); ffma2(hd[1][3], w3, v1);
            }
            __syncwarp();
#pragma unroll
            for (int g = 0; g < 2; g++)
#pragma unroll
                for (int p = 0; p < 4; p++) {
                    const float2 a = unpack2(hd[g][p]);
                    *(float2*)&row[g][8 + 8 * jl + 2 * p] =
                        make_float2(fmaxf(a.x, 0.0f), fmaxf(a.y, 0.0f));
                }
            __syncwarp();
        }
        // ---- decoder layer 2 + loss: px = hd @ Wd2p + bd2p (48-padded) ----
        {
            u64 px[2][3];
#pragma unroll
            for (int i = 0; i < 3; i++) {
                const u64 bv = d2u(((const double*)sbd2)[3 * jl + i]);
                px[0][i] = bv; px[1][i] = bv;
            }
#pragma unroll 4
            for (int k = 0; k < 64; k++) {
                const double* wr = (const double*)&sWd2[k * 48 + 6 * jl];
                const u64 w0 = d2u(wr[0]), w1 = d2u(wr[1]), w2 = d2u(wr[2]);
                const u64 v0 = splat2(row[0][8 + k]), v1 = splat2(row[1][8 + k]);
                ffma2(px[0][0], w0, v0); ffma2(px[0][1], w1, v0); ffma2(px[0][2], w2, v0);
                ffma2(px[1][0], w0, v1); ffma2(px[1][1], w1, v1); ffma2(px[1][2], w2, v1);
            }
#pragma unroll
            for (int g = 0; g < 2; g++) {
                const float* xb = x    + (size_t)bg[g] * TT * DD + (size_t)t * DD;
                const float* mb = mask + (size_t)bg[g] * TT * DD + (size_t)t * DD;
#pragma unroll
                for (int i = 0; i < 3; i++) {
                    const int d0 = 6 * jl + 2 * i;
                    if (d0 < 44) {
                        const float2 xv = *(const float2*)&xb[d0];
                        const float2 mv = *(const float2*)&mb[d0];
                        const float2 p  = unpack2(px[g][i]);
                        float da = xv.x - p.x, db = xv.y - p.y;
                        da = (xv.x * mv.x != 0.0f) ? 0.0f : da;
                        db = (xv.y * mv.y != 0.0f) ? 0.0f : db;
                        sse[g] += da * da + db * db;
                    }
                }
            }
        }

        // ---- RK4 step ----
        if (t < TT - 1) {
            float zac[2] = {zr[0], zr[1]};
#pragma unroll 1
            for (int s = 0; s < 4; s++) {
                const float wco = (s == 0 || s == 3) ? dt / 6.0f : dt / 3.0f;
                const float cco = (s == 2) ? dt : 0.5f * dt;
                // h1 = elu(zin @ Wf1 + bf1); zin in row[g][0..8)
                u64 a1[2][4];
#pragma unroll
                for (int p = 0; p < 4; p++) {
                    const u64 bv = d2u(((const double*)sbf1)[4 * jl + p]);
                    a1[0][p] = bv; a1[1][p] = bv;
                }
#pragma unroll
                for (int k = 0; k < 8; k++) {
                    const double2* wr = (const double2*)&sWf1[k * 64 + 8 * jl];
                    const double2 wa = wr[0], wb = wr[1];
                    const u64 w0 = d2u(wa.x), w1 = d2u(wa.y), w2 = d2u(wb.x), w3 = d2u(wb.y);
                    const u64 v0 = splat2(row[0][k]), v1 = splat2(row[1][k]);
                    ffma2(a1[0][0], w0, v0); ffma2(a1[0][1], w1, v0);
                    ffma2(a1[0][2], w2, v0); ffma2(a1[0][3], w3, v0);
                    ffma2(a1[1][0], w0, v1); ffma2(a1[1][1], w1, v1);
                    ffma2(a1[1][2], w2, v1); ffma2(a1[1][3], w3, v1);
                }
                __syncwarp();
#pragma unroll
                for (int g = 0; g < 2; g++)
#pragma unroll
                    for (int p = 0; p < 4; p++) {
                        const float2 a = unpack2(a1[g][p]);
                        const float ea = (a.x > 0.0f) ? a.x : (__expf(a.x) - 1.0f);
                        const float eb = (a.y > 0.0f) ? a.y : (__expf(a.y) - 1.0f);
                        *(float2*)&row[g][8 + 8 * jl + 2 * p] = make_float2(ea, eb);
                    }
                __syncwarp();
                // h2 = elu(h1 @ Wf2 + bf2)
                u64 a2[2][4];
#pragma unroll
                for (int p = 0; p < 4; p++) {
                    const u64 bv = d2u(((const double*)sbf2)[4 * jl + p]);
                    a2[0][p] = bv; a2[1][p] = bv;
                }
#pragma unroll 4
                for (int k = 0; k < 64; k++) {
                    const double2* wr = (const double2*)&sWf2[k * 64 + 8 * jl];
                    const double2 wa = wr[0], wb = wr[1];
                    const u64 w0 = d2u(wa.x), w1 = d2u(wa.y), w2 = d2u(wb.x), w3 = d2u(wb.y);
                    const u64 v0 = splat2(row[0][8 + k]), v1 = splat2(row[1][8 + k]);
                    ffma2(a2[0][0], w0, v0); ffma2(a2[0][1], w1, v0);
                    ffma2(a2[0][2], w2, v0); ffma2(a2[0][3], w3, v0);
                    ffma2(a2[1][0], w0, v1); ffma2(a2[1][1], w1, v1);
                    ffma2(a2[1][2], w2, v1); ffma2(a2[1][3], w3, v1);
                }
#pragma unroll
                for (int g = 0; g < 2; g++)
#pragma unroll
                    for (int p = 0; p < 4; p++) {
                        const float2 a = unpack2(a2[g][p]);
                        const float ea = (a.x > 0.0f) ? a.x : (__expf(a.x) - 1.0f);
                        const float eb = (a.y > 0.0f) ? a.y : (__expf(a.y) - 1.0f);
                        *(float2*)&row[g][72 + 8 * jl + 2 * p] = make_float2(ea, eb);
                    }
                __syncwarp();
                // fout[jl] = sum_k h2[k] * Wf3[k][jl] + bf3[jl]
                float f0 = 0.0f, f1 = 0.0f;
#pragma unroll 4
                for (int k = 0; k < 64; k++) {
                    const float w = sWf3[k * 8 + jl];
                    f0 += row[0][72 + k] * w;
                    f1 += row[1][72 + k] * w;
                }
                const float bf = sbf3[jl];
                f0 += bf; f1 += bf;
                zac[0] += wco * f0; zac[1] += wco * f1;
                if (s < 3) {
                    row[0][jl] = zr[0] + cco * f0;
                    row[1][jl] = zr[1] + cco * f1;
                } else {
                    zr[0] = zac[0]; zr[1] = zac[1];
                    row[0][jl] = zr[0];
                    row[1][jl] = zr[1];
                }
                __syncwarp();
            }
        }
    }

    // reduce SSE over the 8-lane group, write per-element loss
#pragma unroll
    for (int g = 0; g < 2; g++) {
        float s = sse[g];
        s += __shfl_xor_sync(0xffffffffu, s, 1);
        s += __shfl_xor_sync(0xffffffffu, s, 2);
        s += __shfl_xor_sync(0xffffffffu, s, 4);
        if (jl == 0) {
            const float nlv = 2.0f * logf(0.3f);
            const float l2p = logf(6.283185307179586f);
            const float logpx = -0.5f * ((float)(TT * DD) * (l2p + nlv) + s / expf(nlv));
            g_perb[bg[g]] = -logpx + g_kl[bg[g]];
        }
    }
}

// ---------------------------------------------------------------------------
// Kernel 3: mean reduction -> d_out[0]
// ---------------------------------------------------------------------------
__global__ void reduce_kernel(float* __restrict__ out)
{
    __shared__ float s[1024];
    const int tid = threadIdx.x;
    float v = 0.0f;
    for (int i = tid; i < BB; i += 1024) v += g_perb[i];
    s[tid] = v;
    __syncthreads();
    for (int st = 512; st > 0; st >>= 1) {
        if (tid < st) s[tid] += s[tid + st];
        __syncthreads();
    }
    if (tid == 0) out[0] = s[0] / (float)BB;
}

// ---------------------------------------------------------------------------
extern "C" void kernel_launch(void* const* d_in, const int* in_sizes, int n_in,
                              void* d_out, int out_size)
{
    const float* x    = (const float*)d_in[0];
    const float* mask = (const float*)d_in[1];
    const float* eps  = (const float*)d_in[2];
    const float* Wi2h = (const float*)d_in[3];
    const float* bi2h = (const float*)d_in[4];
    const float* Wh2o = (const float*)d_in[5];
    const float* bh2o = (const float*)d_in[6];
    const float* Wf1  = (const float*)d_in[7];
    const float* bf1  = (const float*)d_in[8];
    const float* Wf2  = (const float*)d_in[9];
    const float* bf2  = (const float*)d_in[10];
    const float* Wf3  = (const float*)d_in[11];
    const float* bf3  = (const float*)d_in[12];
    const float* Wd1  = (const float*)d_in[13];
    const float* bd1  = (const float*)d_in[14];
    const float* Wd2  = (const float*)d_in[15];
    const float* bd2  = (const float*)d_in[16];

    enc_kernel<<<BB / 32, 128>>>(x, mask, eps, Wi2h, bi2h, Wh2o, bh2o);
    ode_kernel<<<BB / 32, 128>>>(x, mask, Wf1, bf1, Wf2, bf2, Wf3, bf3,
                                 Wd1, bd1, Wd2, bd2);
    reduce_kernel<<<1, 1024>>>((float*)d_out);
}